// round 5
// baseline (speedup 1.0000x reference)
#include <cuda_runtime.h>
#include <cuda_fp16.h>
#include <cstdint>

#define NUM_LEVELS 16
#define BASE_RES   16
#define TABLE_MASK ((1u << 19) - 1u)
#define P1 2654435761u
#define P2 805459861u

#define FP16_SCALE    8192.0f       // 2^13, exact
#define FP16_INVSCALE 1.220703125e-4f  // 2^-13, exact

// Dense z-pair records for levels 0..2 (kept fp32 -> exact).
#define D0_SIZE (17 * 17 * 16)
#define D1_SIZE (33 * 33 * 32)
#define D2_SIZE (65 * 65 * 64)
#define D1_BASE D0_SIZE
#define D2_BASE (D0_SIZE + D1_SIZE)
#define D_TOTAL (D0_SIZE + D1_SIZE + D2_SIZE)

__device__ float4 g_dense[D_TOTAL];

// fp16 copies of hashed-level tables (levels 3..15), entry = half2 packed in u32.
#define NUM_HASHED 13
#define HTAB_ENTRIES (NUM_HASHED << 19)     // 6,815,744 entries (~27.3 MB)
__device__ uint32_t g_htab[HTAB_ENTRIES];

__global__ __launch_bounds__(256)
void convert_tables_kernel(const float* __restrict__ tables)
{
    int t = blockIdx.x * blockDim.x + threadIdx.x;
    if (t >= HTAB_ENTRIES) return;
    int l = 3 + (t >> 19);
    int i = t & TABLE_MASK;
    const float2* __restrict__ tbl = (const float2*)tables + ((size_t)l << 19);
    float2 v = __ldg(tbl + i);
    half2 h = __floats2half2_rn(v.x * FP16_SCALE, v.y * FP16_SCALE);
    g_htab[t] = *reinterpret_cast<uint32_t*>(&h);
}

__global__ __launch_bounds__(256)
void build_dense_kernel(const float* __restrict__ tables)
{
    int t = blockIdx.x * blockDim.x + threadIdx.x;
    if (t >= D_TOTAL) return;

    int l, rem, R;
    if (t < D1_BASE)      { l = 0; rem = t;           R = 16; }
    else if (t < D2_BASE) { l = 1; rem = t - D1_BASE; R = 32; }
    else                  { l = 2; rem = t - D2_BASE; R = 64; }

    int z  = rem % R;
    int xy = rem / R;
    int y  = xy % (R + 1);
    int x  = xy / (R + 1);

    uint32_t hxy = (uint32_t)x ^ ((uint32_t)y * P1);
    uint32_t hz  = (uint32_t)z * P2;
    uint32_t i0 = (hxy ^ hz        ^ (uint32_t)l) & TABLE_MASK;
    uint32_t i1 = (hxy ^ (hz + P2) ^ (uint32_t)l) & TABLE_MASK;

    const float2* __restrict__ tbl = (const float2*)tables + ((size_t)l << 19);
    float2 e0 = __ldg(tbl + i0);
    float2 e1 = __ldg(tbl + i1);
    g_dense[t] = make_float4(e0.x, e0.y, e1.x, e1.y);
}

__device__ __forceinline__ float2 unpack_h2(uint32_t u)
{
    half2 h = *reinterpret_cast<half2*>(&u);
    return __half22float2(h);
}

__global__ __launch_bounds__(256)
void hash_encode_kernel(const float* __restrict__ x,
                        float* __restrict__ out,
                        int N)
{
    int gid = blockIdx.x * blockDim.x + threadIdx.x;
    int n = gid >> 4;
    if (n >= N) return;
    int l = gid & 15;

    float px = __ldg(x + 3 * n + 0);
    float py = __ldg(x + 3 * n + 1);
    float pz = __ldg(x + 3 * n + 2);

    const float HI = 0.999999f;
    float xn = fminf(fmaxf((px + 1.0f) * 0.5f, 0.0f), HI);
    float yn = fminf(fmaxf((py + 1.0f) * 0.5f, 0.0f), HI);
    float zn = fminf(fmaxf((pz + 1.0f) * 0.5f, 0.0f), HI);

    float res = (float)(BASE_RES << l);

    float sx = xn * res, sy = yn * res, sz = zn * res;
    float fx0 = floorf(sx), fy0 = floorf(sy), fz0 = floorf(sz);
    float fx = sx - fx0, fy = sy - fy0, fz = sz - fz0;

    int cx = (int)fx0, cy = (int)fy0, cz = (int)fz0;

    float wx1 = fx, wx0 = 1.0f - fx;
    float wy1 = fy, wy0 = 1.0f - fy;
    float wz1 = fz, wz0 = 1.0f - fz;

    float a0, a1;

    if (l < 3) {
        // ---- dense path: 4 aligned 16B z-pair loads (exact fp32) ----
        int R   = BASE_RES << l;
        int Rp1 = R + 1;
        int base = (l == 0) ? 0 : (l == 1) ? D1_BASE : D2_BASE;

        int r00 = base + (cx * Rp1 + cy) * R + cz;
        int r01 = r00 + R;
        int r10 = r00 + Rp1 * R;
        int r11 = r10 + R;

        float4 q00 = __ldg(g_dense + r00);
        float4 q01 = __ldg(g_dense + r01);
        float4 q10 = __ldg(g_dense + r10);
        float4 q11 = __ldg(g_dense + r11);

        float w;
        w = wx0 * wy0 * wz0; a0 = w * q00.x;            a1 = w * q00.y;
        w = wx0 * wy0 * wz1; a0 = fmaf(w, q00.z, a0);   a1 = fmaf(w, q00.w, a1);
        w = wx0 * wy1 * wz0; a0 = fmaf(w, q01.x, a0);   a1 = fmaf(w, q01.y, a1);
        w = wx0 * wy1 * wz1; a0 = fmaf(w, q01.z, a0);   a1 = fmaf(w, q01.w, a1);
        w = wx1 * wy0 * wz0; a0 = fmaf(w, q10.x, a0);   a1 = fmaf(w, q10.y, a1);
        w = wx1 * wy0 * wz1; a0 = fmaf(w, q10.z, a0);   a1 = fmaf(w, q10.w, a1);
        w = wx1 * wy1 * wz0; a0 = fmaf(w, q11.x, a0);   a1 = fmaf(w, q11.y, a1);
        w = wx1 * wy1 * wz1; a0 = fmaf(w, q11.z, a0);   a1 = fmaf(w, q11.w, a1);
    } else {
        // ---- hashed path on fp16 tables ----
        uint32_t hx0 = (uint32_t)cx;
        uint32_t hx1 = hx0 + 1u;
        uint32_t hy0 = (uint32_t)cy * P1;
        uint32_t hy1 = hy0 + P1;
        uint32_t hzb = (uint32_t)cz * P2;
        uint32_t hz0 = hzb        ^ (uint32_t)l;
        uint32_t hz1 = (hzb + P2) ^ (uint32_t)l;

        const uint32_t* __restrict__ tbl = g_htab + ((size_t)(l - 3) << 19);

        uint32_t hj[4];
        hj[0] = hy0 ^ hz0;
        hj[1] = hy0 ^ hz1;
        hj[2] = hy1 ^ hz0;
        hj[3] = hy1 ^ hz1;

        uint32_t t = hx0 ^ hx1;       // 2^(trailing_ones(cx)+1) - 1
        float2 e[8];                  // e[j] = x0 corner, e[j+4] = x1 corner

        if (t == 1u) {
            // pair {idx, idx^1} -> one aligned 8B load per combo
            const uint2* __restrict__ tbl2 = (const uint2*)tbl;
#pragma unroll
            for (int j = 0; j < 4; ++j) {
                uint32_t i0 = (hx0 ^ hj[j]) & TABLE_MASK;
                uint2 q = __ldg(tbl2 + (i0 >> 1));
                uint32_t a = i0 & 1u;
                uint32_t ea = a ? q.y : q.x;
                uint32_t eb = a ? q.x : q.y;
                e[j]     = unpack_h2(ea);
                e[j + 4] = unpack_h2(eb);
            }
        } else if (t == 3u) {
            // pair {idx, idx^3} inside one aligned 16B group
            const uint4* __restrict__ tbl4 = (const uint4*)tbl;
#pragma unroll
            for (int j = 0; j < 4; ++j) {
                uint32_t i0 = (hx0 ^ hj[j]) & TABLE_MASK;
                uint4 q = __ldg(tbl4 + (i0 >> 2));
                uint32_t a = i0 & 3u;
                uint32_t ea = (a & 2u) ? ((a & 1u) ? q.w : q.z)
                                       : ((a & 1u) ? q.y : q.x);
                uint32_t eb = (a & 2u) ? ((a & 1u) ? q.x : q.y)
                                       : ((a & 1u) ? q.z : q.w);
                e[j]     = unpack_h2(ea);
                e[j + 4] = unpack_h2(eb);
            }
        } else {
            // fallback: two 4B gathers per combo
#pragma unroll
            for (int j = 0; j < 4; ++j) {
                e[j]     = unpack_h2(__ldg(tbl + ((hx0 ^ hj[j]) & TABLE_MASK)));
                e[j + 4] = unpack_h2(__ldg(tbl + ((hx1 ^ hj[j]) & TABLE_MASK)));
            }
        }

        float w[8];
#pragma unroll
        for (int k = 0; k < 8; ++k) {
            w[k] = ((k & 4) ? wx1 : wx0)
                 * ((k & 2) ? wy1 : wy0)
                 * ((k & 1) ? wz1 : wz0);
        }
        a0 = 0.0f; a1 = 0.0f;
#pragma unroll
        for (int k = 0; k < 8; ++k) {
            a0 = fmaf(w[k], e[k].x, a0);
            a1 = fmaf(w[k], e[k].y, a1);
        }
        a0 *= FP16_INVSCALE;
        a1 *= FP16_INVSCALE;
    }

    float2* o = (float2*)(out + (size_t)n * (NUM_LEVELS * 2));
    o[l] = make_float2(a0, a1);
}

extern "C" void kernel_launch(void* const* d_in, const int* in_sizes, int n_in,
                              void* d_out, int out_size)
{
    const float* x      = (const float*)d_in[0];
    const float* tables = (const float*)d_in[1];
    float* out          = (float*)d_out;

    int N = in_sizes[0] / 3;

    convert_tables_kernel<<<(HTAB_ENTRIES + 255) / 256, 256>>>(tables);
    build_dense_kernel<<<(D_TOTAL + 255) / 256, 256>>>(tables);

    int total = N * NUM_LEVELS;
    hash_encode_kernel<<<(total + 255) / 256, 256>>>(x, out, N);
}

// round 7
// speedup vs baseline: 1.1172x; 1.1172x over previous
#include <cuda_runtime.h>
#include <cuda_fp16.h>
#include <cstdint>

#define NUM_LEVELS 16
#define BASE_RES   16
#define TABLE_MASK ((1u << 19) - 1u)
#define P1 2654435761u
#define P2 805459861u

#define FP16_SCALE    8192.0f          // 2^13, exact
#define FP16_INVSCALE 1.220703125e-4f  // 2^-13, exact

// ---- dense quad records for levels 0..2 ----
// record(x,y,z) = 4 scaled-fp16 entries: (y,z),(y,z+1),(y+1,z),(y+1,z+1)
// grid: x in [0,R], y in [0,R-1], z in [0,R-1]  -> (R+1)*R*R records
#define Q0_SIZE (17 * 16 * 16)      // 4352
#define Q1_SIZE (33 * 32 * 32)      // 33792
#define Q2_SIZE (65 * 64 * 64)      // 266240
#define Q1_BASE Q0_SIZE
#define Q2_BASE (Q0_SIZE + Q1_SIZE)
#define Q_TOTAL (Q0_SIZE + Q1_SIZE + Q2_SIZE)   // 304384 (~4.9 MB)

__device__ uint4 g_quad[Q_TOTAL];

// fp16 copies of hashed-level tables (levels 3..15), entry = half2 in u32.
#define NUM_HASHED 13
#define HTAB_ENTRIES (NUM_HASHED << 19)         // ~27.3 MB
__device__ uint32_t g_htab[HTAB_ENTRIES];

__device__ __forceinline__ uint32_t pack_h2(float a, float b)
{
    half2 h = __floats2half2_rn(a * FP16_SCALE, b * FP16_SCALE);
    return *reinterpret_cast<uint32_t*>(&h);
}

__global__ __launch_bounds__(256)
void convert_tables_kernel(const float* __restrict__ tables)
{
    // one thread converts 4 consecutive entries (levels are contiguous in src)
    int t = blockIdx.x * blockDim.x + threadIdx.x;
    if (t >= (HTAB_ENTRIES >> 2)) return;
    // source: entries (3<<19) + 4t .. +3  -> float4 index (3<<18) + 2t
    const float4* __restrict__ src = (const float4*)tables + (3 << 18);
    float4 v0 = __ldg(src + 2 * t);
    float4 v1 = __ldg(src + 2 * t + 1);
    uint4 o;
    o.x = pack_h2(v0.x, v0.y);
    o.y = pack_h2(v0.z, v0.w);
    o.z = pack_h2(v1.x, v1.y);
    o.w = pack_h2(v1.z, v1.w);
    ((uint4*)g_htab)[t] = o;
}

__global__ __launch_bounds__(256)
void build_quad_kernel(const float* __restrict__ tables)
{
    int t = blockIdx.x * blockDim.x + threadIdx.x;
    if (t >= Q_TOTAL) return;

    int l, rem, R;
    if (t < Q1_BASE)      { l = 0; rem = t;           R = 16; }
    else if (t < Q2_BASE) { l = 1; rem = t - Q1_BASE; R = 32; }
    else                  { l = 2; rem = t - Q2_BASE; R = 64; }

    int z = rem % R;
    int y = (rem / R) % R;
    int x = rem / (R * R);

    uint32_t hx  = (uint32_t)x ^ (uint32_t)l;
    uint32_t hy0 = (uint32_t)y * P1;
    uint32_t hy1 = hy0 + P1;
    uint32_t hz0 = (uint32_t)z * P2;
    uint32_t hz1 = hz0 + P2;

    const float2* __restrict__ tbl = (const float2*)tables + ((size_t)l << 19);
    float2 e00 = __ldg(tbl + ((hx ^ hy0 ^ hz0) & TABLE_MASK));
    float2 e01 = __ldg(tbl + ((hx ^ hy0 ^ hz1) & TABLE_MASK));
    float2 e10 = __ldg(tbl + ((hx ^ hy1 ^ hz0) & TABLE_MASK));
    float2 e11 = __ldg(tbl + ((hx ^ hy1 ^ hz1) & TABLE_MASK));

    uint4 o;
    o.x = pack_h2(e00.x, e00.y);
    o.y = pack_h2(e01.x, e01.y);
    o.z = pack_h2(e10.x, e10.y);
    o.w = pack_h2(e11.x, e11.y);
    g_quad[t] = o;
}

__device__ __forceinline__ float2 unpack_h2(uint32_t u)
{
    half2 h = *reinterpret_cast<half2*>(&u);
    return __half22float2(h);
}

__global__ __launch_bounds__(256)
void hash_encode_kernel(const float* __restrict__ x,
                        float* __restrict__ out,
                        int N)
{
    int gid = blockIdx.x * blockDim.x + threadIdx.x;
    int n = gid >> 4;
    if (n >= N) return;
    int l = gid & 15;

    float px = __ldg(x + 3 * n + 0);
    float py = __ldg(x + 3 * n + 1);
    float pz = __ldg(x + 3 * n + 2);

    const float HI = 0.999999f;
    float xn = fminf(fmaxf((px + 1.0f) * 0.5f, 0.0f), HI);
    float yn = fminf(fmaxf((py + 1.0f) * 0.5f, 0.0f), HI);
    float zn = fminf(fmaxf((pz + 1.0f) * 0.5f, 0.0f), HI);

    float res = (float)(BASE_RES << l);

    float sx = xn * res, sy = yn * res, sz = zn * res;
    float fx0 = floorf(sx), fy0 = floorf(sy), fz0 = floorf(sz);
    float fx = sx - fx0, fy = sy - fy0, fz = sz - fz0;

    int cx = (int)fx0, cy = (int)fy0, cz = (int)fz0;

    float wx1 = fx, wx0 = 1.0f - fx;
    float wy1 = fy, wy0 = 1.0f - fy;
    float wz1 = fz, wz0 = 1.0f - fz;

    float a0, a1;

    if (l < 3) {
        // ---- dense path: 2 aligned 16B quad loads (x and x+1) ----
        int R = BASE_RES << l;
        int base = (l == 0) ? 0 : (l == 1) ? Q1_BASE : Q2_BASE;

        int r0 = base + (cx * R + cy) * R + cz;
        int r1 = r0 + R * R;                    // x+1

        uint4 q0 = __ldg(g_quad + r0);
        uint4 q1 = __ldg(g_quad + r1);

        float2 e;
        float w;
        w = wx0 * wy0 * wz0; e = unpack_h2(q0.x); a0 = w * e.x;          a1 = w * e.y;
        w = wx0 * wy0 * wz1; e = unpack_h2(q0.y); a0 = fmaf(w, e.x, a0); a1 = fmaf(w, e.y, a1);
        w = wx0 * wy1 * wz0; e = unpack_h2(q0.z); a0 = fmaf(w, e.x, a0); a1 = fmaf(w, e.y, a1);
        w = wx0 * wy1 * wz1; e = unpack_h2(q0.w); a0 = fmaf(w, e.x, a0); a1 = fmaf(w, e.y, a1);
        w = wx1 * wy0 * wz0; e = unpack_h2(q1.x); a0 = fmaf(w, e.x, a0); a1 = fmaf(w, e.y, a1);
        w = wx1 * wy0 * wz1; e = unpack_h2(q1.y); a0 = fmaf(w, e.x, a0); a1 = fmaf(w, e.y, a1);
        w = wx1 * wy1 * wz0; e = unpack_h2(q1.z); a0 = fmaf(w, e.x, a0); a1 = fmaf(w, e.y, a1);
        w = wx1 * wy1 * wz1; e = unpack_h2(q1.w); a0 = fmaf(w, e.x, a0); a1 = fmaf(w, e.y, a1);
    } else {
        // ---- hashed path on fp16 tables ----
        uint32_t hx0 = (uint32_t)cx;
        uint32_t hx1 = hx0 + 1u;
        uint32_t hy0 = (uint32_t)cy * P1;
        uint32_t hy1 = hy0 + P1;
        uint32_t hzb = (uint32_t)cz * P2;
        uint32_t hz0 = hzb        ^ (uint32_t)l;
        uint32_t hz1 = (hzb + P2) ^ (uint32_t)l;

        const uint32_t* __restrict__ tbl = g_htab + ((size_t)(l - 3) << 19);

        uint32_t hj[4];
        hj[0] = hy0 ^ hz0;
        hj[1] = hy0 ^ hz1;
        hj[2] = hy1 ^ hz0;
        hj[3] = hy1 ^ hz1;

        uint32_t t = hx0 ^ hx1;
        float2 e[8];

        if (t == 1u) {
            const uint2* __restrict__ tbl2 = (const uint2*)tbl;
#pragma unroll
            for (int j = 0; j < 4; ++j) {
                uint32_t i0 = (hx0 ^ hj[j]) & TABLE_MASK;
                uint2 q = __ldg(tbl2 + (i0 >> 1));
                uint32_t a = i0 & 1u;
                e[j]     = unpack_h2(a ? q.y : q.x);
                e[j + 4] = unpack_h2(a ? q.x : q.y);
            }
        } else if (t == 3u) {
            const uint4* __restrict__ tbl4 = (const uint4*)tbl;
#pragma unroll
            for (int j = 0; j < 4; ++j) {
                uint32_t i0 = (hx0 ^ hj[j]) & TABLE_MASK;
                uint4 q = __ldg(tbl4 + (i0 >> 2));
                uint32_t a = i0 & 3u;
                uint32_t ea = (a & 2u) ? ((a & 1u) ? q.w : q.z)
                                       : ((a & 1u) ? q.y : q.x);
                uint32_t eb = (a & 2u) ? ((a & 1u) ? q.x : q.y)
                                       : ((a & 1u) ? q.z : q.w);
                e[j]     = unpack_h2(ea);
                e[j + 4] = unpack_h2(eb);
            }
        } else {
#pragma unroll
            for (int j = 0; j < 4; ++j) {
                e[j]     = unpack_h2(__ldg(tbl + ((hx0 ^ hj[j]) & TABLE_MASK)));
                e[j + 4] = unpack_h2(__ldg(tbl + ((hx1 ^ hj[j]) & TABLE_MASK)));
            }
        }

        float w[8];
#pragma unroll
        for (int k = 0; k < 8; ++k) {
            w[k] = ((k & 4) ? wx1 : wx0)
                 * ((k & 2) ? wy1 : wy0)
                 * ((k & 1) ? wz1 : wz0);
        }
        a0 = 0.0f; a1 = 0.0f;
#pragma unroll
        for (int k = 0; k < 8; ++k) {
            a0 = fmaf(w[k], e[k].x, a0);
            a1 = fmaf(w[k], e[k].y, a1);
        }
    }

    a0 *= FP16_INVSCALE;
    a1 *= FP16_INVSCALE;

    float2* o = (float2*)(out + (size_t)n * (NUM_LEVELS * 2));
    o[l] = make_float2(a0, a1);
}

extern "C" void kernel_launch(void* const* d_in, const int* in_sizes, int n_in,
                              void* d_out, int out_size)
{
    const float* x      = (const float*)d_in[0];
    const float* tables = (const float*)d_in[1];
    float* out          = (float*)d_out;

    int N = in_sizes[0] / 3;

    convert_tables_kernel<<<((HTAB_ENTRIES >> 2) + 255) / 256, 256>>>(tables);
    build_quad_kernel<<<(Q_TOTAL + 255) / 256, 256>>>(tables);

    int total = N * NUM_LEVELS;
    hash_encode_kernel<<<(total + 255) / 256, 256>>>(x, out, N);
}